// round 1
// baseline (speedup 1.0000x reference)
#include <cuda_runtime.h>
#include <cuda_bf16.h>

// Problem constants
#define BB 2
#define TT 2048
#define CC 2048
#define NH 16
#define NKV 4
#define GRP 4
#define HS 128
#define WIN 1024
#define SNK 4

// Scratch (device globals; allocation APIs are forbidden)
__device__ float g_q[(size_t)BB * TT * CC];          // (B,T,NH,HS)
__device__ float g_k[(size_t)BB * TT * NKV * HS];    // (B,T,NKV,HS)
__device__ float g_v[(size_t)BB * TT * NKV * HS];
__device__ float g_y[(size_t)BB * TT * CC];          // (B,T,NH,HS)

// ---------------------------------------------------------------------------
// SGEMM (NT): C[m,n] = sum_k A[m,k] * B[n,k]
// A: MxK row-major, B: NxK row-major, C: MxN row-major.
// 128x128 block tile, BK=16, 256 threads, 8x8 micro-tile.
// M % 128 == 0, N % 128 == 0, K % 16 == 0 (true for all our shapes).
// ---------------------------------------------------------------------------
__global__ void __launch_bounds__(256) sgemm_nt(
    const float* __restrict__ A, const float* __restrict__ B,
    float* __restrict__ C, int M, int N, int K)
{
    __shared__ float As[16][128];
    __shared__ float Bs[16][128];

    const int tid = threadIdx.x;
    const int m0 = blockIdx.y * 128;
    const int n0 = blockIdx.x * 128;
    const int row_base = (tid >> 4) * 8;
    const int col_base = (tid & 15) * 8;

    const float* Ab = A + (size_t)m0 * K;
    const float* Bb = B + (size_t)n0 * K;

    float acc[8][8];
#pragma unroll
    for (int i = 0; i < 8; ++i)
#pragma unroll
        for (int j = 0; j < 8; ++j) acc[i][j] = 0.0f;

    for (int k0 = 0; k0 < K; k0 += 16) {
        // Load A tile (128x16) and B tile (128x16), store transposed [k][mn]
#pragma unroll
        for (int it = 0; it < 2; ++it) {
            int idx = tid + it * 256;       // 0..511 (512 float4 per tile)
            int r = idx >> 2;               // 0..127
            int kq = (idx & 3) * 4;         // 0,4,8,12
            float4 av = *(const float4*)&Ab[(size_t)r * K + k0 + kq];
            As[kq + 0][r] = av.x; As[kq + 1][r] = av.y;
            As[kq + 2][r] = av.z; As[kq + 3][r] = av.w;
            float4 bv = *(const float4*)&Bb[(size_t)r * K + k0 + kq];
            Bs[kq + 0][r] = bv.x; Bs[kq + 1][r] = bv.y;
            Bs[kq + 2][r] = bv.z; Bs[kq + 3][r] = bv.w;
        }
        __syncthreads();

#pragma unroll
        for (int kk = 0; kk < 16; ++kk) {
            float4 a0 = *(const float4*)&As[kk][row_base];
            float4 a1 = *(const float4*)&As[kk][row_base + 4];
            float4 b0 = *(const float4*)&Bs[kk][col_base];
            float4 b1 = *(const float4*)&Bs[kk][col_base + 4];
            float a[8] = {a0.x, a0.y, a0.z, a0.w, a1.x, a1.y, a1.z, a1.w};
            float b[8] = {b0.x, b0.y, b0.z, b0.w, b1.x, b1.y, b1.z, b1.w};
#pragma unroll
            for (int i = 0; i < 8; ++i)
#pragma unroll
                for (int j = 0; j < 8; ++j)
                    acc[i][j] = fmaf(a[i], b[j], acc[i][j]);
        }
        __syncthreads();
    }

#pragma unroll
    for (int i = 0; i < 8; ++i) {
        float* Crow = C + (size_t)(m0 + row_base + i) * N + n0 + col_base;
        float4 o0 = {acc[i][0], acc[i][1], acc[i][2], acc[i][3]};
        float4 o1 = {acc[i][4], acc[i][5], acc[i][6], acc[i][7]};
        *(float4*)Crow = o0;
        *(float4*)(Crow + 4) = o1;
    }
}

// ---------------------------------------------------------------------------
// Flash-style GQA attention with sliding window + sinks.
// Block: (q_tile of 64, head, batch). 256 threads.
// Smem: Qs[128][68] (transposed, pre-scaled), Ks[128][68] (transposed),
//       Vs[64][128], Ss[64][68].
// Each thread: 4x4 score fragment, 4 rows x 8 cols of O accumulator.
// ---------------------------------------------------------------------------
#define QS_OFF 0
#define KS_OFF (128 * 68)
#define VS_OFF (KS_OFF + 128 * 68)
#define SS_OFF (VS_OFF + 64 * 128)
#define ATTN_SMEM_FLOATS (SS_OFF + 64 * 68)
#define ATTN_SMEM_BYTES (ATTN_SMEM_FLOATS * 4)

__global__ void __launch_bounds__(256) attn_kernel(
    const float* __restrict__ q, const float* __restrict__ k,
    const float* __restrict__ v, float* __restrict__ y)
{
    extern __shared__ float smem[];
    float* Qs = smem + QS_OFF;   // [128][68], Qs[d][r]
    float* Ks = smem + KS_OFF;   // [128][68], Ks[d][c]
    float* Vs = smem + VS_OFF;   // [64][128], Vs[c][d]
    float* Ss = smem + SS_OFF;   // [64][68]

    const int b = blockIdx.z;
    const int h = blockIdx.y;
    const int qb = blockIdx.x;
    const int q0 = qb * 64;
    const int kvh = h / GRP;

    const int tid = threadIdx.x;
    const int rg = tid >> 4;          // 0..15 (row group)
    const int l16 = tid & 15;         // 0..15
    const int r_base = rg * 4;        // score rows
    const int c_base = l16 * 4;       // score cols
    const int c_o = l16 * 8;          // O cols

    const float scale = 0.088388347648318440550f; // 1/sqrt(128)

    // Load Q tile transposed + pre-scaled
    const float* qbase = q + ((size_t)(b * TT + q0) * NH + h) * HS;
#pragma unroll
    for (int it = 0; it < 8; ++it) {
        int idx = tid + it * 256;    // 0..2047
        int r = idx >> 5;            // 0..63
        int d = (idx & 31) * 4;
        float4 qv = *(const float4*)&qbase[(size_t)r * (NH * HS) + d];
        Qs[(d + 0) * 68 + r] = qv.x * scale;
        Qs[(d + 1) * 68 + r] = qv.y * scale;
        Qs[(d + 2) * 68 + r] = qv.z * scale;
        Qs[(d + 3) * 68 + r] = qv.w * scale;
    }

    float O[4][8];
#pragma unroll
    for (int i = 0; i < 4; ++i)
#pragma unroll
        for (int e = 0; e < 8; ++e) O[i][e] = 0.0f;
    float mst[4] = {-1e30f, -1e30f, -1e30f, -1e30f};
    float lst[4] = {0.0f, 0.0f, 0.0f, 0.0f};

    // Tile enumeration: window tiles [kb_start .. qb], plus tile 0 for sinks
    int lo = q0 - (WIN - 1);
    int kb_start = (lo > 0) ? (lo >> 6) : 0;
    int kb_end = qb;
    bool do_sink = (kb_start > 0);
    int ntiles = (kb_end - kb_start + 1) + (do_sink ? 1 : 0);

    for (int tt = 0; tt < ntiles; ++tt) {
        int kb;
        if (do_sink) kb = (tt == 0) ? 0 : (kb_start + tt - 1);
        else         kb = kb_start + tt;
        const int k0 = kb * 64;

        __syncthreads(); // previous PV done before overwriting Ks/Vs/Ss

        const float* kbase = k + ((size_t)(b * TT + k0) * NKV + kvh) * HS;
        const float* vbase = v + ((size_t)(b * TT + k0) * NKV + kvh) * HS;
#pragma unroll
        for (int it = 0; it < 8; ++it) {
            int idx = tid + it * 256;
            int r = idx >> 5;
            int d = (idx & 31) * 4;
            float4 kv4 = *(const float4*)&kbase[(size_t)r * (NKV * HS) + d];
            Ks[(d + 0) * 68 + r] = kv4.x;
            Ks[(d + 1) * 68 + r] = kv4.y;
            Ks[(d + 2) * 68 + r] = kv4.z;
            Ks[(d + 3) * 68 + r] = kv4.w;
            float4 vv4 = *(const float4*)&vbase[(size_t)r * (NKV * HS) + d];
            *(float4*)&Vs[r * 128 + d] = vv4;
        }
        __syncthreads();

        // S = Qs^T @ Ks (4x4 fragment per thread)
        float s[4][4];
#pragma unroll
        for (int i = 0; i < 4; ++i)
#pragma unroll
            for (int j = 0; j < 4; ++j) s[i][j] = 0.0f;

#pragma unroll 8
        for (int kk = 0; kk < 128; ++kk) {
            float4 qf = *(const float4*)&Qs[kk * 68 + r_base];
            float4 kf = *(const float4*)&Ks[kk * 68 + c_base];
            float qa[4] = {qf.x, qf.y, qf.z, qf.w};
            float ka[4] = {kf.x, kf.y, kf.z, kf.w};
#pragma unroll
            for (int i = 0; i < 4; ++i)
#pragma unroll
                for (int j = 0; j < 4; ++j)
                    s[i][j] = fmaf(qa[i], ka[j], s[i][j]);
        }

        // Mask: visible = (kj<=qi) && (kj >= qi-(WIN-1) || kj < SNK)
#pragma unroll
        for (int i = 0; i < 4; ++i) {
            int qi = q0 + r_base + i;
#pragma unroll
            for (int j = 0; j < 4; ++j) {
                int kj = k0 + c_base + j;
                bool vis = (kj <= qi) && ((kj >= qi - (WIN - 1)) || (kj < SNK));
                if (!vis) s[i][j] = -1e30f;
            }
        }

        // Online softmax per row (reduce over 16 lanes of the row group)
        float alpha[4];
        float p[4][4];
#pragma unroll
        for (int i = 0; i < 4; ++i) {
            float rmax = fmaxf(fmaxf(s[i][0], s[i][1]), fmaxf(s[i][2], s[i][3]));
#pragma unroll
            for (int off = 8; off >= 1; off >>= 1)
                rmax = fmaxf(rmax, __shfl_xor_sync(0xFFFFFFFFu, rmax, off));
            float mnew = fmaxf(mst[i], rmax);
            alpha[i] = __expf(mst[i] - mnew);
            mst[i] = mnew;
            float rsum = 0.0f;
#pragma unroll
            for (int j = 0; j < 4; ++j) {
                p[i][j] = __expf(s[i][j] - mnew);
                rsum += p[i][j];
            }
#pragma unroll
            for (int off = 8; off >= 1; off >>= 1)
                rsum += __shfl_xor_sync(0xFFFFFFFFu, rsum, off);
            lst[i] = lst[i] * alpha[i] + rsum;
        }

        // Scale O, stash P to shared
#pragma unroll
        for (int i = 0; i < 4; ++i) {
#pragma unroll
            for (int e = 0; e < 8; ++e) O[i][e] *= alpha[i];
            float4 p4 = {p[i][0], p[i][1], p[i][2], p[i][3]};
            *(float4*)&Ss[(r_base + i) * 68 + c_base] = p4;
        }
        __syncthreads();

        // O += P @ V
#pragma unroll 4
        for (int j4 = 0; j4 < 64; j4 += 4) {
            float pr[4][4];
#pragma unroll
            for (int i = 0; i < 4; ++i) {
                float4 pv = *(const float4*)&Ss[(r_base + i) * 68 + j4];
                pr[i][0] = pv.x; pr[i][1] = pv.y; pr[i][2] = pv.z; pr[i][3] = pv.w;
            }
#pragma unroll
            for (int jj = 0; jj < 4; ++jj) {
                float4 v0 = *(const float4*)&Vs[(j4 + jj) * 128 + c_o];
                float4 v1 = *(const float4*)&Vs[(j4 + jj) * 128 + c_o + 4];
                float vv[8] = {v0.x, v0.y, v0.z, v0.w, v1.x, v1.y, v1.z, v1.w};
#pragma unroll
                for (int i = 0; i < 4; ++i) {
                    float pij = pr[i][jj];
#pragma unroll
                    for (int e = 0; e < 8; ++e)
                        O[i][e] = fmaf(pij, vv[e], O[i][e]);
                }
            }
        }
    }

    // Normalize and write y (B,T,NH,HS)
#pragma unroll
    for (int i = 0; i < 4; ++i) {
        float inv = 1.0f / lst[i];
        float* yrow = y + ((size_t)(b * TT + q0 + r_base + i) * NH + h) * HS + c_o;
        float4 o0 = {O[i][0] * inv, O[i][1] * inv, O[i][2] * inv, O[i][3] * inv};
        float4 o1 = {O[i][4] * inv, O[i][5] * inv, O[i][6] * inv, O[i][7] * inv};
        *(float4*)yrow = o0;
        *(float4*)(yrow + 4) = o1;
    }
}

// ---------------------------------------------------------------------------
extern "C" void kernel_launch(void* const* d_in, const int* in_sizes, int n_in,
                              void* d_out, int out_size)
{
    const float* x  = (const float*)d_in[0];
    const float* Wq = (const float*)d_in[1];
    const float* Wk = (const float*)d_in[2];
    const float* Wv = (const float*)d_in[3];
    const float* Wo = (const float*)d_in[4];
    float* out = (float*)d_out;

    float *qp, *kp, *vp, *yp;
    cudaGetSymbolAddress((void**)&qp, g_q);
    cudaGetSymbolAddress((void**)&kp, g_k);
    cudaGetSymbolAddress((void**)&vp, g_v);
    cudaGetSymbolAddress((void**)&yp, g_y);

    const int M = BB * TT;  // 4096

    // Projections
    sgemm_nt<<<dim3(CC / 128, M / 128), 256>>>(x, Wq, qp, M, CC, CC);
    sgemm_nt<<<dim3((NKV * HS) / 128, M / 128), 256>>>(x, Wk, kp, M, NKV * HS, CC);
    sgemm_nt<<<dim3((NKV * HS) / 128, M / 128), 256>>>(x, Wv, vp, M, NKV * HS, CC);

    // Attention
    cudaFuncSetAttribute(attn_kernel, cudaFuncAttributeMaxDynamicSharedMemorySize,
                         ATTN_SMEM_BYTES);
    attn_kernel<<<dim3(TT / 64, NH, BB), 256, ATTN_SMEM_BYTES>>>(qp, kp, vp, yp);

    // Output projection
    sgemm_nt<<<dim3(CC / 128, M / 128), 256>>>(yp, Wo, out, M, CC, CC);
}

// round 3
// speedup vs baseline: 1.6173x; 1.6173x over previous
#include <cuda_runtime.h>
#include <cuda_bf16.h>
#include <cstdint>

// Problem constants
#define BB 2
#define TT 2048
#define CC 2048
#define NH 16
#define NKV 4
#define GRP 4
#define HS 128
#define WIN 1024
#define SNK 4

// Scratch (device globals; allocation APIs are forbidden)
__device__ float g_q[(size_t)BB * TT * CC];          // (B,T,NH,HS)
__device__ float g_k[(size_t)BB * TT * NKV * HS];    // (B,T,NKV,HS)
__device__ float g_v[(size_t)BB * TT * NKV * HS];
__device__ float g_y[(size_t)BB * TT * CC];          // (B,T,NH,HS)
// bf16 split buffers (A side reused for x and y; B side for weights)
__device__ __nv_bfloat16 g_ahi[(size_t)BB * TT * CC];
__device__ __nv_bfloat16 g_alo[(size_t)BB * TT * CC];
__device__ __nv_bfloat16 g_bhi[(size_t)CC * CC];
__device__ __nv_bfloat16 g_blo[(size_t)CC * CC];

// ---------------------------------------------------------------------------
// Helpers
// ---------------------------------------------------------------------------
__device__ __forceinline__ uint32_t smem_u32(const void* p) {
    uint32_t a;
    asm("{ .reg .u64 t; cvta.to.shared.u64 t, %1; cvt.u32.u64 %0, t; }"
        : "=r"(a) : "l"(p));
    return a;
}

#define CP_ASYNC16(dst, src) \
    asm volatile("cp.async.cg.shared.global [%0], [%1], 16;" :: "r"(dst), "l"(src))
#define CP_ASYNC_COMMIT() asm volatile("cp.async.commit_group;" ::: "memory")
#define CP_ASYNC_WAIT1()  asm volatile("cp.async.wait_group 1;" ::: "memory")

__device__ __forceinline__ void ldsm4(uint32_t* r, uint32_t addr) {
    asm volatile("ldmatrix.sync.aligned.m8n8.x4.shared.b16 {%0,%1,%2,%3}, [%4];"
                 : "=r"(r[0]), "=r"(r[1]), "=r"(r[2]), "=r"(r[3]) : "r"(addr));
}

__device__ __forceinline__ void mma16816(float* d, const uint32_t* a,
                                         uint32_t b0, uint32_t b1) {
    asm volatile(
        "mma.sync.aligned.m16n8k16.row.col.f32.bf16.bf16.f32 "
        "{%0,%1,%2,%3}, {%4,%5,%6,%7}, {%8,%9}, {%0,%1,%2,%3};"
        : "+f"(d[0]), "+f"(d[1]), "+f"(d[2]), "+f"(d[3])
        : "r"(a[0]), "r"(a[1]), "r"(a[2]), "r"(a[3]), "r"(b0), "r"(b1));
}

// ---------------------------------------------------------------------------
// Split fp32 -> (bf16 hi, bf16 lo) with exact residual
// ---------------------------------------------------------------------------
__global__ void __launch_bounds__(256) split_kernel(
    const float* __restrict__ in, __nv_bfloat16* __restrict__ hi,
    __nv_bfloat16* __restrict__ lo, int n4)
{
    int i = blockIdx.x * blockDim.x + threadIdx.x;
    if (i >= n4) return;
    float4 v = ((const float4*)in)[i];
    __nv_bfloat16 h0 = __float2bfloat16_rn(v.x);
    __nv_bfloat16 h1 = __float2bfloat16_rn(v.y);
    __nv_bfloat16 h2 = __float2bfloat16_rn(v.z);
    __nv_bfloat16 h3 = __float2bfloat16_rn(v.w);
    __nv_bfloat16 l0 = __float2bfloat16_rn(v.x - __bfloat162float(h0));
    __nv_bfloat16 l1 = __float2bfloat16_rn(v.y - __bfloat162float(h1));
    __nv_bfloat16 l2 = __float2bfloat16_rn(v.z - __bfloat162float(h2));
    __nv_bfloat16 l3 = __float2bfloat16_rn(v.w - __bfloat162float(h3));
    __nv_bfloat162* hp = (__nv_bfloat162*)(hi + (size_t)i * 4);
    __nv_bfloat162* lp = (__nv_bfloat162*)(lo + (size_t)i * 4);
    hp[0] = __nv_bfloat162(h0, h1);
    hp[1] = __nv_bfloat162(h2, h3);
    lp[0] = __nv_bfloat162(l0, l1);
    lp[1] = __nv_bfloat162(l2, l3);
}

// ---------------------------------------------------------------------------
// bf16 mma.sync 3-product split GEMM (NT): C[m,n] = sum_k A[m,k]*B[n,k].
// CTA tile 128x128, BK=32 bf16, 8 warps (4x2), warp tile 32x64.
// Smem rows padded to 80B (5x16B, 5 coprime 8 => conflict-free ldmatrix).
// 3-stage cp.async pipeline, 40KB/stage.
// ---------------------------------------------------------------------------
#define GBM 128
#define GBN 128
#define GBK 32
#define ROWB 80u                      // bytes per smem row (32 bf16 + 16B pad)
#define TILE_B (128u * ROWB)          // 10240 bytes per tile
#define STG_B (4u * TILE_B)           // Ahi, Alo, Bhi, Blo
#define GSTAGES 3
#define GEMM_DYN_SMEM (GSTAGES * STG_B)

__global__ void __launch_bounds__(256) gemm_mma(
    const __nv_bfloat16* __restrict__ Ahi, const __nv_bfloat16* __restrict__ Alo,
    const __nv_bfloat16* __restrict__ Bhi, const __nv_bfloat16* __restrict__ Blo,
    float* __restrict__ C, int M, int N, int K)
{
    extern __shared__ char dsmem[];
    const uint32_t sbase = smem_u32(dsmem);

    const int tid = threadIdx.x;
    const int wid = tid >> 5;
    const int lane = tid & 31;
    const int wr = wid >> 1;          // warp row 0..3 (32 rows each)
    const int wc = wid & 1;           // warp col 0..1 (64 cols each)
    const int m0 = blockIdx.y * GBM;
    const int n0 = blockIdx.x * GBN;
    const int niter = K / GBK;

    // Per-thread cp.async slots: row = tid>>2 (0..63, +64), chunk c = tid&3
    const int lrow = tid >> 2;
    const int lc = tid & 3;

    auto load_stage = [&](int s, int kc) {
        uint32_t st = sbase + (uint32_t)s * STG_B;
        size_t kof = (size_t)kc * GBK + lc * 8;
        const __nv_bfloat16* aH = Ahi + (size_t)(m0 + lrow) * K + kof;
        const __nv_bfloat16* aL = Alo + (size_t)(m0 + lrow) * K + kof;
        const __nv_bfloat16* bH = Bhi + (size_t)(n0 + lrow) * K + kof;
        const __nv_bfloat16* bL = Blo + (size_t)(n0 + lrow) * K + kof;
        uint32_t d = st + (uint32_t)lrow * ROWB + (uint32_t)lc * 16;
        CP_ASYNC16(d + 0u * TILE_B, aH);
        CP_ASYNC16(d + 1u * TILE_B, aL);
        CP_ASYNC16(d + 2u * TILE_B, bH);
        CP_ASYNC16(d + 3u * TILE_B, bL);
        uint32_t d2 = d + 64u * ROWB;
        size_t g2 = (size_t)64 * K;
        CP_ASYNC16(d2 + 0u * TILE_B, aH + g2);
        CP_ASYNC16(d2 + 1u * TILE_B, aL + g2);
        CP_ASYNC16(d2 + 2u * TILE_B, bH + g2);
        CP_ASYNC16(d2 + 3u * TILE_B, bL + g2);
    };

    float acc[2][8][4];
#pragma unroll
    for (int f = 0; f < 2; ++f)
#pragma unroll
        for (int j = 0; j < 8; ++j)
#pragma unroll
            for (int e = 0; e < 4; ++e) acc[f][j][e] = 0.0f;

    // Prologue
    load_stage(0, 0);
    CP_ASYNC_COMMIT();
    load_stage(1, 1);
    CP_ASYNC_COMMIT();

    const int fr = lane & 15;         // ldmatrix row within 16
    const int fh = lane >> 4;         // 0/1 -> +8 k (chunk +1)

    for (int i = 0; i < niter; ++i) {
        const int s = i % GSTAGES;
        CP_ASYNC_WAIT1();
        __syncthreads();

        if (i + 2 < niter) load_stage((i + 2) % GSTAGES, i + 2);
        CP_ASYNC_COMMIT();

        const uint32_t stA = sbase + (uint32_t)s * STG_B;
        const uint32_t stB = stA + 2u * TILE_B;

#pragma unroll
        for (int ks = 0; ks < 2; ++ks) {
            const uint32_t chunk = (uint32_t)((ks << 1) + fh) * 16u;

            uint32_t ah[2][4], al[2][4];
#pragma unroll
            for (int f = 0; f < 2; ++f) {
                uint32_t ad = stA + (uint32_t)(wr * 32 + f * 16 + fr) * ROWB + chunk;
                ldsm4(ah[f], ad);
                ldsm4(al[f], ad + TILE_B);
            }

#pragma unroll
            for (int j4 = 0; j4 < 4; ++j4) {
                uint32_t bd = stB + (uint32_t)(wc * 64 + j4 * 16 + fr) * ROWB + chunk;
                uint32_t bh[4], bl[4];
                ldsm4(bh, bd);
                ldsm4(bl, bd + TILE_B);
#pragma unroll
                for (int f = 0; f < 2; ++f) {
                    mma16816(acc[f][2 * j4 + 0], ah[f], bh[0], bh[2]);
                    mma16816(acc[f][2 * j4 + 1], ah[f], bh[1], bh[3]);
                    mma16816(acc[f][2 * j4 + 0], ah[f], bl[0], bl[2]);
                    mma16816(acc[f][2 * j4 + 1], ah[f], bl[1], bl[3]);
                    mma16816(acc[f][2 * j4 + 0], al[f], bh[0], bh[2]);
                    mma16816(acc[f][2 * j4 + 1], al[f], bh[1], bh[3]);
                }
            }
        }
    }

    // Epilogue: direct fp32 stores (d0,d1 -> row, d2,d3 -> row+8)
    const int er = lane >> 2;
    const int ec = (lane & 3) * 2;
#pragma unroll
    for (int f = 0; f < 2; ++f) {
        const int row = m0 + wr * 32 + f * 16 + er;
#pragma unroll
        for (int j = 0; j < 8; ++j) {
            const int col = n0 + wc * 64 + j * 8 + ec;
            float2 v0 = {acc[f][j][0], acc[f][j][1]};
            float2 v1 = {acc[f][j][2], acc[f][j][3]};
            *(float2*)&C[(size_t)row * N + col] = v0;
            *(float2*)&C[(size_t)(row + 8) * N + col] = v1;
        }
    }
}

// ---------------------------------------------------------------------------
// Flash-style GQA attention with sliding window + sinks (unchanged).
// ---------------------------------------------------------------------------
#define QS_OFF 0
#define KS_OFF (128 * 68)
#define VS_OFF (KS_OFF + 128 * 68)
#define SS_OFF (VS_OFF + 64 * 128)
#define ATTN_SMEM_FLOATS (SS_OFF + 64 * 68)
#define ATTN_SMEM_BYTES (ATTN_SMEM_FLOATS * 4)

__global__ void __launch_bounds__(256) attn_kernel(
    const float* __restrict__ q, const float* __restrict__ k,
    const float* __restrict__ v, float* __restrict__ y)
{
    extern __shared__ float smem[];
    float* Qs = smem + QS_OFF;   // [128][68], Qs[d][r]
    float* Ks = smem + KS_OFF;   // [128][68], Ks[d][c]
    float* Vs = smem + VS_OFF;   // [64][128], Vs[c][d]
    float* Ss = smem + SS_OFF;   // [64][68]

    const int b = blockIdx.z;
    const int h = blockIdx.y;
    const int qb = blockIdx.x;
    const int q0 = qb * 64;
    const int kvh = h / GRP;

    const int tid = threadIdx.x;
    const int rg = tid >> 4;
    const int l16 = tid & 15;
    const int r_base = rg * 4;
    const int c_base = l16 * 4;
    const int c_o = l16 * 8;

    const float scale = 0.088388347648318440550f; // 1/sqrt(128)

    const float* qbase = q + ((size_t)(b * TT + q0) * NH + h) * HS;
#pragma unroll
    for (int it = 0; it < 8; ++it) {
        int idx = tid + it * 256;
        int r = idx >> 5;
        int d = (idx & 31) * 4;
        float4 qv = *(const float4*)&qbase[(size_t)r * (NH * HS) + d];
        Qs[(d + 0) * 68 + r] = qv.x * scale;
        Qs[(d + 1) * 68 + r] = qv.y * scale;
        Qs[(d + 2) * 68 + r] = qv.z * scale;
        Qs[(d + 3) * 68 + r] = qv.w * scale;
    }

    float O[4][8];
#pragma unroll
    for (int i = 0; i < 4; ++i)
#pragma unroll
        for (int e = 0; e < 8; ++e) O[i][e] = 0.0f;
    float mst[4] = {-1e30f, -1e30f, -1e30f, -1e30f};
    float lst[4] = {0.0f, 0.0f, 0.0f, 0.0f};

    int lo = q0 - (WIN - 1);
    int kb_start = (lo > 0) ? (lo >> 6) : 0;
    int kb_end = qb;
    bool do_sink = (kb_start > 0);
    int ntiles = (kb_end - kb_start + 1) + (do_sink ? 1 : 0);

    for (int tt = 0; tt < ntiles; ++tt) {
        int kb;
        if (do_sink) kb = (tt == 0) ? 0 : (kb_start + tt - 1);
        else         kb = kb_start + tt;
        const int k0 = kb * 64;

        __syncthreads();

        const float* kbase = k + ((size_t)(b * TT + k0) * NKV + kvh) * HS;
        const float* vbase = v + ((size_t)(b * TT + k0) * NKV + kvh) * HS;
#pragma unroll
        for (int it = 0; it < 8; ++it) {
            int idx = tid + it * 256;
            int r = idx >> 5;
            int d = (idx & 31) * 4;
            float4 kv4 = *(const float4*)&kbase[(size_t)r * (NKV * HS) + d];
            Ks[(d + 0) * 68 + r] = kv4.x;
            Ks[(d + 1) * 68 + r] = kv4.y;
            Ks[(d + 2) * 68 + r] = kv4.z;
            Ks[(d + 3) * 68 + r] = kv4.w;
            float4 vv4 = *(const float4*)&vbase[(size_t)r * (NKV * HS) + d];
            *(float4*)&Vs[r * 128 + d] = vv4;
        }
        __syncthreads();

        float s[4][4];
#pragma unroll
        for (int i = 0; i < 4; ++i)
#pragma unroll
            for (int j = 0; j < 4; ++j) s[i][j] = 0.0f;

#pragma unroll 8
        for (int kk = 0; kk < 128; ++kk) {
            float4 qf = *(const float4*)&Qs[kk * 68 + r_base];
            float4 kf = *(const float4*)&Ks[kk * 68 + c_base];
            float qa[4] = {qf.x, qf.y, qf.z, qf.w};
            float ka[4] = {kf.x, kf.y, kf.z, kf.w};
#pragma unroll
            for (int i = 0; i < 4; ++i)
#pragma unroll
                for (int j = 0; j < 4; ++j)
                    s[i][j] = fmaf(qa[i], ka[j], s[i][j]);
        }

#pragma unroll
        for (int i = 0; i < 4; ++i) {
            int qi = q0 + r_base + i;
#pragma unroll
            for (int j = 0; j < 4; ++j) {
                int kj = k0 + c_base + j;
                bool vis = (kj <= qi) && ((kj >= qi - (WIN - 1)) || (kj < SNK));
                if (!vis) s[i][j] = -1e30f;
            }
        }

        float alpha[4];
        float p[4][4];
#pragma unroll
        for (int i = 0; i < 4; ++i) {
            float rmax = fmaxf(fmaxf(s[i][0], s[i][1]), fmaxf(s[i][2], s[i][3]));
#pragma unroll
            for (int off = 8; off >= 1; off >>= 1)
                rmax = fmaxf(rmax, __shfl_xor_sync(0xFFFFFFFFu, rmax, off));
            float mnew = fmaxf(mst[i], rmax);
            alpha[i] = __expf(mst[i] - mnew);
            mst[i] = mnew;
            float rsum = 0.0f;
#pragma unroll
            for (int j = 0; j < 4; ++j) {
                p[i][j] = __expf(s[i][j] - mnew);
                rsum += p[i][j];
            }
#pragma unroll
            for (int off = 8; off >= 1; off >>= 1)
                rsum += __shfl_xor_sync(0xFFFFFFFFu, rsum, off);
            lst[i] = lst[i] * alpha[i] + rsum;
        }

#pragma unroll
        for (int i = 0; i < 4; ++i) {
#pragma unroll
            for (int e = 0; e < 8; ++e) O[i][e] *= alpha[i];
            float4 p4 = {p[i][0], p[i][1], p[i][2], p[i][3]};
            *(float4*)&Ss[(r_base + i) * 68 + c_base] = p4;
        }
        __syncthreads();

#pragma unroll 4
        for (int j4 = 0; j4 < 64; j4 += 4) {
            float pr[4][4];
#pragma unroll
            for (int i = 0; i < 4; ++i) {
                float4 pv = *(const float4*)&Ss[(r_base + i) * 68 + j4];
                pr[i][0] = pv.x; pr[i][1] = pv.y; pr[i][2] = pv.z; pr[i][3] = pv.w;
            }
#pragma unroll
            for (int jj = 0; jj < 4; ++jj) {
                float4 v0 = *(const float4*)&Vs[(j4 + jj) * 128 + c_o];
                float4 v1 = *(const float4*)&Vs[(j4 + jj) * 128 + c_o + 4];
                float vv[8] = {v0.x, v0.y, v0.z, v0.w, v1.x, v1.y, v1.z, v1.w};
#pragma unroll
                for (int i = 0; i < 4; ++i) {
                    float pij = pr[i][jj];
#pragma unroll
                    for (int e = 0; e < 8; ++e)
                        O[i][e] = fmaf(pij, vv[e], O[i][e]);
                }
            }
        }
    }

#pragma unroll
    for (int i = 0; i < 4; ++i) {
        float inv = 1.0f / lst[i];
        float* yrow = y + ((size_t)(b * TT + q0 + r_base + i) * NH + h) * HS + c_o;
        float4 o0 = {O[i][0] * inv, O[i][1] * inv, O[i][2] * inv, O[i][3] * inv};
        float4 o1 = {O[i][4] * inv, O[i][5] * inv, O[i][6] * inv, O[i][7] * inv};
        *(float4*)yrow = o0;
        *(float4*)(yrow + 4) = o1;
    }
}

// ---------------------------------------------------------------------------
extern "C" void kernel_launch(void* const* d_in, const int* in_sizes, int n_in,
                              void* d_out, int out_size)
{
    const float* x  = (const float*)d_in[0];
    const float* Wq = (const float*)d_in[1];
    const float* Wk = (const float*)d_in[2];
    const float* Wv = (const float*)d_in[3];
    const float* Wo = (const float*)d_in[4];
    float* out = (float*)d_out;

    float *qp, *kp, *vp, *yp;
    cudaGetSymbolAddress((void**)&qp, g_q);
    cudaGetSymbolAddress((void**)&kp, g_k);
    cudaGetSymbolAddress((void**)&vp, g_v);
    cudaGetSymbolAddress((void**)&yp, g_y);
    __nv_bfloat16 *ahi, *alo, *bhi, *blo;
    cudaGetSymbolAddress((void**)&ahi, g_ahi);
    cudaGetSymbolAddress((void**)&alo, g_alo);
    cudaGetSymbolAddress((void**)&bhi, g_bhi);
    cudaGetSymbolAddress((void**)&blo, g_blo);

    const int M = BB * TT;  // 4096

    cudaFuncSetAttribute(gemm_mma, cudaFuncAttributeMaxDynamicSharedMemorySize,
                         GEMM_DYN_SMEM);

    // Split x (shared by Q/K/V projections)
    split_kernel<<<(M * CC / 4 + 255) / 256, 256>>>(x, ahi, alo, M * CC / 4);

    // Q projection
    split_kernel<<<(CC * CC / 4 + 255) / 256, 256>>>(Wq, bhi, blo, CC * CC / 4);
    gemm_mma<<<dim3(CC / 128, M / 128), 256, GEMM_DYN_SMEM>>>(
        ahi, alo, bhi, blo, qp, M, CC, CC);

    // K projection
    split_kernel<<<(NKV * HS * CC / 4 + 255) / 256, 256>>>(Wk, bhi, blo, NKV * HS * CC / 4);
    gemm_mma<<<dim3((NKV * HS) / 128, M / 128), 256, GEMM_DYN_SMEM>>>(
        ahi, alo, bhi, blo, kp, M, NKV * HS, CC);

    // V projection
    split_kernel<<<(NKV * HS * CC / 4 + 255) / 256, 256>>>(Wv, bhi, blo, NKV * HS * CC / 4);
    gemm_mma<<<dim3((NKV * HS) / 128, M / 128), 256, GEMM_DYN_SMEM>>>(
        ahi, alo, bhi, blo, vp, M, NKV * HS, CC);

    // Attention
    cudaFuncSetAttribute(attn_kernel, cudaFuncAttributeMaxDynamicSharedMemorySize,
                         ATTN_SMEM_BYTES);
    attn_kernel<<<dim3(TT / 64, NH, BB), 256, ATTN_SMEM_BYTES>>>(qp, kp, vp, yp);

    // Output projection: split y (reuse A buffers) and Wo
    split_kernel<<<(M * CC / 4 + 255) / 256, 256>>>(yp, ahi, alo, M * CC / 4);
    split_kernel<<<(CC * CC / 4 + 255) / 256, 256>>>(Wo, bhi, blo, CC * CC / 4);
    gemm_mma<<<dim3(CC / 128, M / 128), 256, GEMM_DYN_SMEM>>>(
        ahi, alo, bhi, blo, out, M, CC, CC);
}

// round 4
// speedup vs baseline: 2.5583x; 1.5818x over previous
#include <cuda_runtime.h>
#include <cuda_bf16.h>
#include <cstdint>

// Problem constants
#define BB 2
#define TT 2048
#define CC 2048
#define NH 16
#define NKV 4
#define GRP 4
#define HS 128
#define WIN 1024
#define SNK 4

// Scratch (device globals; allocation APIs are forbidden)
__device__ float g_q[(size_t)BB * TT * CC];          // (B,T,NH,HS)
__device__ float g_k[(size_t)BB * TT * NKV * HS];    // (B,T,NKV,HS)
__device__ float g_v[(size_t)BB * TT * NKV * HS];
__device__ float g_y[(size_t)BB * TT * CC];          // (B,T,NH,HS)
// bf16 split buffers for GEMMs
__device__ __nv_bfloat16 g_ahi[(size_t)BB * TT * CC];
__device__ __nv_bfloat16 g_alo[(size_t)BB * TT * CC];
__device__ __nv_bfloat16 g_bhi[(size_t)CC * CC];
__device__ __nv_bfloat16 g_blo[(size_t)CC * CC];
// bf16 split buffers for attention
__device__ __nv_bfloat16 g_qhi[(size_t)BB * TT * CC];
__device__ __nv_bfloat16 g_qlo[(size_t)BB * TT * CC];
__device__ __nv_bfloat16 g_khi[(size_t)BB * TT * NKV * HS];
__device__ __nv_bfloat16 g_klo[(size_t)BB * TT * NKV * HS];
__device__ __nv_bfloat16 g_vhi[(size_t)BB * TT * NKV * HS];
__device__ __nv_bfloat16 g_vlo[(size_t)BB * TT * NKV * HS];

// ---------------------------------------------------------------------------
// Helpers
// ---------------------------------------------------------------------------
__device__ __forceinline__ uint32_t smem_u32(const void* p) {
    uint32_t a;
    asm("{ .reg .u64 t; cvta.to.shared.u64 t, %1; cvt.u32.u64 %0, t; }"
        : "=r"(a) : "l"(p));
    return a;
}

#define CP_ASYNC16(dst, src) \
    asm volatile("cp.async.cg.shared.global [%0], [%1], 16;" :: "r"(dst), "l"(src))
#define CP_ASYNC_COMMIT() asm volatile("cp.async.commit_group;" ::: "memory")
#define CP_ASYNC_WAIT1()  asm volatile("cp.async.wait_group 1;" ::: "memory")

__device__ __forceinline__ void ldsm4(uint32_t* r, uint32_t addr) {
    asm volatile("ldmatrix.sync.aligned.m8n8.x4.shared.b16 {%0,%1,%2,%3}, [%4];"
                 : "=r"(r[0]), "=r"(r[1]), "=r"(r[2]), "=r"(r[3]) : "r"(addr));
}

__device__ __forceinline__ void ldsm4t(uint32_t* r, uint32_t addr) {
    asm volatile("ldmatrix.sync.aligned.m8n8.x4.trans.shared.b16 {%0,%1,%2,%3}, [%4];"
                 : "=r"(r[0]), "=r"(r[1]), "=r"(r[2]), "=r"(r[3]) : "r"(addr));
}

__device__ __forceinline__ void mma16816(float* d, const uint32_t* a,
                                         uint32_t b0, uint32_t b1) {
    asm volatile(
        "mma.sync.aligned.m16n8k16.row.col.f32.bf16.bf16.f32 "
        "{%0,%1,%2,%3}, {%4,%5,%6,%7}, {%8,%9}, {%0,%1,%2,%3};"
        : "+f"(d[0]), "+f"(d[1]), "+f"(d[2]), "+f"(d[3])
        : "r"(a[0]), "r"(a[1]), "r"(a[2]), "r"(a[3]), "r"(b0), "r"(b1));
}

__device__ __forceinline__ uint32_t pack_bf16x2(float a, float b) {
    __nv_bfloat162 h = __float22bfloat162_rn(make_float2(a, b));
    return *(uint32_t*)&h;
}

// ---------------------------------------------------------------------------
// Split fp32 -> (bf16 hi, bf16 lo) with exact residual
// ---------------------------------------------------------------------------
__global__ void __launch_bounds__(256) split_kernel(
    const float* __restrict__ in, __nv_bfloat16* __restrict__ hi,
    __nv_bfloat16* __restrict__ lo, int n4)
{
    int i = blockIdx.x * blockDim.x + threadIdx.x;
    if (i >= n4) return;
    float4 v = ((const float4*)in)[i];
    __nv_bfloat16 h0 = __float2bfloat16_rn(v.x);
    __nv_bfloat16 h1 = __float2bfloat16_rn(v.y);
    __nv_bfloat16 h2 = __float2bfloat16_rn(v.z);
    __nv_bfloat16 h3 = __float2bfloat16_rn(v.w);
    __nv_bfloat16 l0 = __float2bfloat16_rn(v.x - __bfloat162float(h0));
    __nv_bfloat16 l1 = __float2bfloat16_rn(v.y - __bfloat162float(h1));
    __nv_bfloat16 l2 = __float2bfloat16_rn(v.z - __bfloat162float(h2));
    __nv_bfloat16 l3 = __float2bfloat16_rn(v.w - __bfloat162float(h3));
    __nv_bfloat162* hp = (__nv_bfloat162*)(hi + (size_t)i * 4);
    __nv_bfloat162* lp = (__nv_bfloat162*)(lo + (size_t)i * 4);
    hp[0] = __nv_bfloat162(h0, h1);
    hp[1] = __nv_bfloat162(h2, h3);
    lp[0] = __nv_bfloat162(l0, l1);
    lp[1] = __nv_bfloat162(l2, l3);
}

// ---------------------------------------------------------------------------
// bf16 mma.sync 3-product split GEMM (NT): C[m,n] = sum_k A[m,k]*B[n,k].
// (unchanged from R3 — validated)
// ---------------------------------------------------------------------------
#define GBM 128
#define GBN 128
#define GBK 32
#define ROWB 80u
#define TILE_B (128u * ROWB)
#define STG_B (4u * TILE_B)
#define GSTAGES 3
#define GEMM_DYN_SMEM (GSTAGES * STG_B)

__global__ void __launch_bounds__(256) gemm_mma(
    const __nv_bfloat16* __restrict__ Ahi, const __nv_bfloat16* __restrict__ Alo,
    const __nv_bfloat16* __restrict__ Bhi, const __nv_bfloat16* __restrict__ Blo,
    float* __restrict__ C, int M, int N, int K)
{
    extern __shared__ char dsmem[];
    const uint32_t sbase = smem_u32(dsmem);

    const int tid = threadIdx.x;
    const int wid = tid >> 5;
    const int lane = tid & 31;
    const int wr = wid >> 1;
    const int wc = wid & 1;
    const int m0 = blockIdx.y * GBM;
    const int n0 = blockIdx.x * GBN;
    const int niter = K / GBK;

    const int lrow = tid >> 2;
    const int lc = tid & 3;

    auto load_stage = [&](int s, int kc) {
        uint32_t st = sbase + (uint32_t)s * STG_B;
        size_t kof = (size_t)kc * GBK + lc * 8;
        const __nv_bfloat16* aH = Ahi + (size_t)(m0 + lrow) * K + kof;
        const __nv_bfloat16* aL = Alo + (size_t)(m0 + lrow) * K + kof;
        const __nv_bfloat16* bH = Bhi + (size_t)(n0 + lrow) * K + kof;
        const __nv_bfloat16* bL = Blo + (size_t)(n0 + lrow) * K + kof;
        uint32_t d = st + (uint32_t)lrow * ROWB + (uint32_t)lc * 16;
        CP_ASYNC16(d + 0u * TILE_B, aH);
        CP_ASYNC16(d + 1u * TILE_B, aL);
        CP_ASYNC16(d + 2u * TILE_B, bH);
        CP_ASYNC16(d + 3u * TILE_B, bL);
        uint32_t d2 = d + 64u * ROWB;
        size_t g2 = (size_t)64 * K;
        CP_ASYNC16(d2 + 0u * TILE_B, aH + g2);
        CP_ASYNC16(d2 + 1u * TILE_B, aL + g2);
        CP_ASYNC16(d2 + 2u * TILE_B, bH + g2);
        CP_ASYNC16(d2 + 3u * TILE_B, bL + g2);
    };

    float acc[2][8][4];
#pragma unroll
    for (int f = 0; f < 2; ++f)
#pragma unroll
        for (int j = 0; j < 8; ++j)
#pragma unroll
            for (int e = 0; e < 4; ++e) acc[f][j][e] = 0.0f;

    load_stage(0, 0);
    CP_ASYNC_COMMIT();
    load_stage(1, 1);
    CP_ASYNC_COMMIT();

    const int fr = lane & 15;
    const int fh = lane >> 4;

    for (int i = 0; i < niter; ++i) {
        const int s = i % GSTAGES;
        CP_ASYNC_WAIT1();
        __syncthreads();

        if (i + 2 < niter) load_stage((i + 2) % GSTAGES, i + 2);
        CP_ASYNC_COMMIT();

        const uint32_t stA = sbase + (uint32_t)s * STG_B;
        const uint32_t stB = stA + 2u * TILE_B;

#pragma unroll
        for (int ks = 0; ks < 2; ++ks) {
            const uint32_t chunk = (uint32_t)((ks << 1) + fh) * 16u;

            uint32_t ah[2][4], al[2][4];
#pragma unroll
            for (int f = 0; f < 2; ++f) {
                uint32_t ad = stA + (uint32_t)(wr * 32 + f * 16 + fr) * ROWB + chunk;
                ldsm4(ah[f], ad);
                ldsm4(al[f], ad + TILE_B);
            }

#pragma unroll
            for (int j4 = 0; j4 < 4; ++j4) {
                uint32_t bd = stB + (uint32_t)(wc * 64 + j4 * 16 + fr) * ROWB + chunk;
                uint32_t bh[4], bl[4];
                ldsm4(bh, bd);
                ldsm4(bl, bd + TILE_B);
#pragma unroll
                for (int f = 0; f < 2; ++f) {
                    mma16816(acc[f][2 * j4 + 0], ah[f], bh[0], bh[2]);
                    mma16816(acc[f][2 * j4 + 1], ah[f], bh[1], bh[3]);
                    mma16816(acc[f][2 * j4 + 0], ah[f], bl[0], bl[2]);
                    mma16816(acc[f][2 * j4 + 1], ah[f], bl[1], bl[3]);
                    mma16816(acc[f][2 * j4 + 0], al[f], bh[0], bh[2]);
                    mma16816(acc[f][2 * j4 + 1], al[f], bh[1], bh[3]);
                }
            }
        }
    }

    const int er = lane >> 2;
    const int ec = (lane & 3) * 2;
#pragma unroll
    for (int f = 0; f < 2; ++f) {
        const int row = m0 + wr * 32 + f * 16 + er;
#pragma unroll
        for (int j = 0; j < 8; ++j) {
            const int col = n0 + wc * 64 + j * 8 + ec;
            float2 v0 = {acc[f][j][0], acc[f][j][1]};
            float2 v1 = {acc[f][j][2], acc[f][j][3]};
            *(float2*)&C[(size_t)row * N + col] = v0;
            *(float2*)&C[(size_t)(row + 8) * N + col] = v1;
        }
    }
}

// ---------------------------------------------------------------------------
// FA2-style GQA attention on tensor cores with hi/lo split.
// CTA: 128 q rows x 1 head. 8 warps, 16 rows each. K-tiles of 64 keys.
// Smem rows: 128 bf16 = 256B + 16B pad = 272B.
// Q (hi+lo) resident; K/V (hi+lo) double-buffered via cp.async.
// ---------------------------------------------------------------------------
#define AROW 272u
#define QL_OFF  (128u * AROW)          // 34816
#define KV_OFF  (2u * 128u * AROW)     // 69632
#define KCOMP   17408u                 // 64*272 per component
#define KV_STG  (4u * KCOMP)           // 69632 per stage
#define ATTN2_SMEM (KV_OFF + 2u * KV_STG)  // 208896

__global__ void __launch_bounds__(256) attn_mma(
    const __nv_bfloat16* __restrict__ qh, const __nv_bfloat16* __restrict__ ql,
    const __nv_bfloat16* __restrict__ kh, const __nv_bfloat16* __restrict__ kl,
    const __nv_bfloat16* __restrict__ vh, const __nv_bfloat16* __restrict__ vl,
    float* __restrict__ y)
{
    extern __shared__ char sm[];
    const uint32_t sb = smem_u32(sm);

    const int b = blockIdx.z;
    const int h = blockIdx.y;
    const int qb = blockIdx.x;
    const int q0 = qb * 128;
    const int kvh = h / GRP;

    const int tid = threadIdx.x;
    const int wid = tid >> 5;
    const int lane = tid & 31;
    const int fr = lane & 15;
    const int fh = lane >> 4;

    const float scale = 0.088388347648318440550f; // 1/sqrt(128)

    // --- Q loads (hi+lo), resident for whole CTA ---
    {
        size_t qbase = ((size_t)(b * TT + q0) * NH + h) * HS;
#pragma unroll
        for (int c = 0; c < 8; ++c) {
            int idx = tid + c * 256;
            int r = idx >> 4;
            int ch = idx & 15;
            uint32_t dst = sb + (uint32_t)r * AROW + (uint32_t)ch * 16;
            const __nv_bfloat16* gq = qh + qbase + (size_t)r * (NH * HS) + ch * 8;
            const __nv_bfloat16* gl = ql + qbase + (size_t)r * (NH * HS) + ch * 8;
            CP_ASYNC16(dst, gq);
            CP_ASYNC16(dst + QL_OFF, gl);
        }
    }
    CP_ASYNC_COMMIT();

    // K/V tile loader (hi+lo each for K and V) into stage buf
    auto load_kv = [&](int buf, int k0t) {
        uint32_t st = sb + KV_OFF + (uint32_t)buf * KV_STG;
        size_t kbase = ((size_t)(b * TT + k0t) * NKV + kvh) * HS;
#pragma unroll
        for (int c = 0; c < 4; ++c) {
            int idx = tid + c * 256;
            int r = idx >> 4;
            int ch = idx & 15;
            size_t g = kbase + (size_t)r * (NKV * HS) + ch * 8;
            uint32_t d = st + (uint32_t)r * AROW + (uint32_t)ch * 16;
            CP_ASYNC16(d + 0u * KCOMP, kh + g);
            CP_ASYNC16(d + 1u * KCOMP, kl + g);
            CP_ASYNC16(d + 2u * KCOMP, vh + g);
            CP_ASYNC16(d + 3u * KCOMP, vl + g);
        }
    };

    // Tile enumeration: optional sink tile (kb 0) first, then window tiles
    int lo = q0 - (WIN - 1);
    int kb_start = (lo > 0) ? (lo >> 6) : 0;
    int kb_end = (q0 + 127) >> 6;
    bool do_sink = (kb_start > 0);
    int ntiles = (kb_end - kb_start + 1) + (do_sink ? 1 : 0);
    auto kb_of = [&](int t) {
        return do_sink ? (t == 0 ? 0 : kb_start + t - 1) : (kb_start + t);
    };

    load_kv(0, kb_of(0) * 64);
    CP_ASYNC_COMMIT();
    if (ntiles > 1) load_kv(1, kb_of(1) * 64);
    CP_ASYNC_COMMIT();

    // State
    float O[16][4];
#pragma unroll
    for (int n = 0; n < 16; ++n)
#pragma unroll
        for (int e = 0; e < 4; ++e) O[n][e] = 0.0f;
    float m0s = -1e30f, m1s = -1e30f;
    float l0s = 0.0f, l1s = 0.0f;

    const int r4 = lane >> 2;         // fragment row within 8
    const int c2 = (lane & 3) * 2;    // fragment col pair base

    for (int t = 0; t < ntiles; ++t) {
        const int k0 = kb_of(t) * 64;
        CP_ASYNC_WAIT1();
        __syncthreads();

        const uint32_t stg = sb + KV_OFF + (uint32_t)(t & 1) * KV_STG;

        // --- S = Q K^T (3-product split), per warp: 16 rows x 64 keys ---
        float S[8][4];
#pragma unroll
        for (int j = 0; j < 8; ++j)
#pragma unroll
            for (int e = 0; e < 4; ++e) S[j][e] = 0.0f;

#pragma unroll
        for (int kc = 0; kc < 8; ++kc) {
            uint32_t qaddr = sb + (uint32_t)(wid * 16 + fr) * AROW
                           + (uint32_t)kc * 32 + (uint32_t)fh * 16;
            uint32_t ah[4], al[4];
            ldsm4(ah, qaddr);
            ldsm4(al, qaddr + QL_OFF);
#pragma unroll
            for (int kg = 0; kg < 4; ++kg) {
                uint32_t kaddr = stg + (uint32_t)(kg * 16 + fr) * AROW
                               + (uint32_t)kc * 32 + (uint32_t)fh * 16;
                uint32_t bh4[4], bl4[4];
                ldsm4(bh4, kaddr);
                ldsm4(bl4, kaddr + KCOMP);
                mma16816(S[2 * kg + 0], ah, bh4[0], bh4[2]);
                mma16816(S[2 * kg + 1], ah, bh4[1], bh4[3]);
                mma16816(S[2 * kg + 0], ah, bl4[0], bl4[2]);
                mma16816(S[2 * kg + 1], ah, bl4[1], bl4[3]);
                mma16816(S[2 * kg + 0], al, bh4[0], bh4[2]);
                mma16816(S[2 * kg + 1], al, bh4[1], bh4[3]);
            }
        }

        // --- scale + mask ---
        bool full = (k0 + 63 <= q0) && (k0 >= q0 + 127 - (WIN - 1));
        int qi0 = q0 + wid * 16 + r4;
        int qi1 = qi0 + 8;
#pragma unroll
        for (int j = 0; j < 8; ++j)
#pragma unroll
            for (int e = 0; e < 4; ++e) S[j][e] *= scale;
        if (!full) {
#pragma unroll
            for (int j = 0; j < 8; ++j) {
                int kj = k0 + 8 * j + c2;
#pragma unroll
                for (int e = 0; e < 2; ++e) {
                    int col = kj + e;
                    bool v0 = (col <= qi0) && ((col >= qi0 - (WIN - 1)) || (col < SNK));
                    bool v1 = (col <= qi1) && ((col >= qi1 - (WIN - 1)) || (col < SNK));
                    if (!v0) S[j][e] = -1e30f;
                    if (!v1) S[j][2 + e] = -1e30f;
                }
            }
        }

        // --- online softmax (rows r4 and r4+8) ---
        float mx0 = -1e30f, mx1 = -1e30f;
#pragma unroll
        for (int j = 0; j < 8; ++j) {
            mx0 = fmaxf(mx0, fmaxf(S[j][0], S[j][1]));
            mx1 = fmaxf(mx1, fmaxf(S[j][2], S[j][3]));
        }
        mx0 = fmaxf(mx0, __shfl_xor_sync(0xFFFFFFFFu, mx0, 1));
        mx0 = fmaxf(mx0, __shfl_xor_sync(0xFFFFFFFFu, mx0, 2));
        mx1 = fmaxf(mx1, __shfl_xor_sync(0xFFFFFFFFu, mx1, 1));
        mx1 = fmaxf(mx1, __shfl_xor_sync(0xFFFFFFFFu, mx1, 2));

        float mn0 = fmaxf(m0s, mx0);
        float mn1 = fmaxf(m1s, mx1);
        float a0 = __expf(m0s - mn0);
        float a1 = __expf(m1s - mn1);
        m0s = mn0; m1s = mn1;

        float sum0 = 0.0f, sum1 = 0.0f;
#pragma unroll
        for (int j = 0; j < 8; ++j) {
            S[j][0] = __expf(S[j][0] - mn0);
            S[j][1] = __expf(S[j][1] - mn0);
            S[j][2] = __expf(S[j][2] - mn1);
            S[j][3] = __expf(S[j][3] - mn1);
            sum0 += S[j][0] + S[j][1];
            sum1 += S[j][2] + S[j][3];
        }
        sum0 += __shfl_xor_sync(0xFFFFFFFFu, sum0, 1);
        sum0 += __shfl_xor_sync(0xFFFFFFFFu, sum0, 2);
        sum1 += __shfl_xor_sync(0xFFFFFFFFu, sum1, 1);
        sum1 += __shfl_xor_sync(0xFFFFFFFFu, sum1, 2);
        l0s = l0s * a0 + sum0;
        l1s = l1s * a1 + sum1;

#pragma unroll
        for (int n = 0; n < 16; ++n) {
            O[n][0] *= a0; O[n][1] *= a0;
            O[n][2] *= a1; O[n][3] *= a1;
        }

        // --- pack P into A-fragments (hi + residual lo) ---
        uint32_t pH[4][4], pL[4][4];
#pragma unroll
        for (int j2 = 0; j2 < 4; ++j2) {
            const int t0 = 2 * j2, t1 = t0 + 1;
            float f[4][2] = {{S[t0][0], S[t0][1]}, {S[t0][2], S[t0][3]},
                             {S[t1][0], S[t1][1]}, {S[t1][2], S[t1][3]}};
#pragma unroll
            for (int g = 0; g < 4; ++g) {
                __nv_bfloat162 hh = __float22bfloat162_rn(make_float2(f[g][0], f[g][1]));
                pH[j2][g] = *(uint32_t*)&hh;
                float r0 = f[g][0] - __bfloat162float(hh.x);
                float r1 = f[g][1] - __bfloat162float(hh.y);
                __nv_bfloat162 ll = __float22bfloat162_rn(make_float2(r0, r1));
                pL[j2][g] = *(uint32_t*)&ll;
            }
        }

        // --- O += P V (3-product split); V via ldmatrix.trans ---
        const uint32_t vbase = stg + 2u * KCOMP;
#pragma unroll
        for (int kc = 0; kc < 4; ++kc) {
#pragma unroll
            for (int dt = 0; dt < 8; ++dt) {
                uint32_t vaddr = vbase + (uint32_t)(kc * 16 + fr) * AROW
                               + (uint32_t)dt * 32 + (uint32_t)fh * 16;
                uint32_t v4h[4], v4l[4];
                ldsm4t(v4h, vaddr);
                ldsm4t(v4l, vaddr + KCOMP);
                mma16816(O[2 * dt + 0], pH[kc], v4h[0], v4h[1]);
                mma16816(O[2 * dt + 1], pH[kc], v4h[2], v4h[3]);
                mma16816(O[2 * dt + 0], pH[kc], v4l[0], v4l[1]);
                mma16816(O[2 * dt + 1], pH[kc], v4l[2], v4l[3]);
                mma16816(O[2 * dt + 0], pL[kc], v4h[0], v4h[1]);
                mma16816(O[2 * dt + 1], pL[kc], v4h[2], v4h[3]);
            }
        }

        __syncthreads();  // done reading this KV buffer
        if (t + 2 < ntiles) load_kv(t & 1, kb_of(t + 2) * 64);
        CP_ASYNC_COMMIT();
    }

    // --- normalize + store ---
    float inv0 = 1.0f / l0s;
    float inv1 = 1.0f / l1s;
    size_t row0 = ((size_t)(b * TT + q0 + wid * 16 + r4) * NH + h) * HS;
    size_t row1 = row0 + (size_t)8 * NH * HS;
#pragma unroll
    for (int n = 0; n < 16; ++n) {
        int d = n * 8 + c2;
        float2 o0 = {O[n][0] * inv0, O[n][1] * inv0};
        float2 o1 = {O[n][2] * inv1, O[n][3] * inv1};
        *(float2*)&y[row0 + d] = o0;
        *(float2*)&y[row1 + d] = o1;
    }
}

// ---------------------------------------------------------------------------
extern "C" void kernel_launch(void* const* d_in, const int* in_sizes, int n_in,
                              void* d_out, int out_size)
{
    const float* x  = (const float*)d_in[0];
    const float* Wq = (const float*)d_in[1];
    const float* Wk = (const float*)d_in[2];
    const float* Wv = (const float*)d_in[3];
    const float* Wo = (const float*)d_in[4];
    float* out = (float*)d_out;

    float *qp, *kp, *vp, *yp;
    cudaGetSymbolAddress((void**)&qp, g_q);
    cudaGetSymbolAddress((void**)&kp, g_k);
    cudaGetSymbolAddress((void**)&vp, g_v);
    cudaGetSymbolAddress((void**)&yp, g_y);
    __nv_bfloat16 *ahi, *alo, *bhi, *blo;
    cudaGetSymbolAddress((void**)&ahi, g_ahi);
    cudaGetSymbolAddress((void**)&alo, g_alo);
    cudaGetSymbolAddress((void**)&bhi, g_bhi);
    cudaGetSymbolAddress((void**)&blo, g_blo);
    __nv_bfloat16 *qhi, *qlo, *khi, *klo, *vhi, *vlo;
    cudaGetSymbolAddress((void**)&qhi, g_qhi);
    cudaGetSymbolAddress((void**)&qlo, g_qlo);
    cudaGetSymbolAddress((void**)&khi, g_khi);
    cudaGetSymbolAddress((void**)&klo, g_klo);
    cudaGetSymbolAddress((void**)&vhi, g_vhi);
    cudaGetSymbolAddress((void**)&vlo, g_vlo);

    const int M = BB * TT;  // 4096

    cudaFuncSetAttribute(gemm_mma, cudaFuncAttributeMaxDynamicSharedMemorySize,
                         GEMM_DYN_SMEM);
    cudaFuncSetAttribute(attn_mma, cudaFuncAttributeMaxDynamicSharedMemorySize,
                         ATTN2_SMEM);

    // Split x (shared A operand for Q/K/V projections)
    split_kernel<<<(M * CC / 4 + 255) / 256, 256>>>(x, ahi, alo, M * CC / 4);

    // Q projection
    split_kernel<<<(CC * CC / 4 + 255) / 256, 256>>>(Wq, bhi, blo, CC * CC / 4);
    gemm_mma<<<dim3(CC / 128, M / 128), 256, GEMM_DYN_SMEM>>>(
        ahi, alo, bhi, blo, qp, M, CC, CC);

    // K projection
    split_kernel<<<(NKV * HS * CC / 4 + 255) / 256, 256>>>(Wk, bhi, blo, NKV * HS * CC / 4);
    gemm_mma<<<dim3((NKV * HS) / 128, M / 128), 256, GEMM_DYN_SMEM>>>(
        ahi, alo, bhi, blo, kp, M, NKV * HS, CC);

    // V projection
    split_kernel<<<(NKV * HS * CC / 4 + 255) / 256, 256>>>(Wv, bhi, blo, NKV * HS * CC / 4);
    gemm_mma<<<dim3((NKV * HS) / 128, M / 128), 256, GEMM_DYN_SMEM>>>(
        ahi, alo, bhi, blo, vp, M, NKV * HS, CC);

    // Split q/k/v for tensor-core attention
    split_kernel<<<(M * CC / 4 + 255) / 256, 256>>>(qp, qhi, qlo, M * CC / 4);
    split_kernel<<<(M * NKV * HS / 4 + 255) / 256, 256>>>(kp, khi, klo, M * NKV * HS / 4);
    split_kernel<<<(M * NKV * HS / 4 + 255) / 256, 256>>>(vp, vhi, vlo, M * NKV * HS / 4);

    // Attention (tensor cores)
    attn_mma<<<dim3(TT / 128, NH, BB), 256, ATTN2_SMEM>>>(
        qhi, qlo, khi, klo, vhi, vlo, yp);

    // Output projection
    split_kernel<<<(M * CC / 4 + 255) / 256, 256>>>(yp, ahi, alo, M * CC / 4);
    split_kernel<<<(CC * CC / 4 + 255) / 256, 256>>>(Wo, bhi, blo, CC * CC / 4);
    gemm_mma<<<dim3(CC / 128, M / 128), 256, GEMM_DYN_SMEM>>>(
        ahi, alo, bhi, blo, out, M, CC, CC);
}